// round 13
// baseline (speedup 1.0000x reference)
#include <cuda_runtime.h>

// ---------------------------------------------------------------------------
// NodeModule_4432406249918  (GB300 / sm_103a)  — R5 structure (best known)
// + PDL overlap of the finalize tail.
//   Kernel A: fused reduce + fill (R5-exact memory ops; adds only a
//             programmatic-launch trigger after each block's last store).
//   Kernel B: warp-per-column finalize, launched with programmatic stream
//             serialization; parks on-SM in cudaGridDependencySynchronize().
//
// out = [ input_under ((n+1)*n,2) | input_over ((n+1)*n,2) | ones(n) | ones(n) ]
//   under_coeffs[j] = sum_k ( nw[k]*Over[k][j] + pw[k]*Under[k][j] ) + bias
//   over_coeffs [j] = sum_k ( pw[k]*Over[k][j] + nw[k]*Under[k][j] ) + bias
//   block b, row i, col c:
//     i==0           -> coeffs[b] * (b==0 ? intervals[0][c] : 1)
//     i==b (0<i<n)   -> intervals[i][c]
//     else           -> 1
// ---------------------------------------------------------------------------

#define KSPLIT 64
#define MAXC   8192   // >= n_vars+1

// transposed: g_part_*[j * KSPLIT + y]  (finalize reads coalesce per warp)
__device__ float g_part_u[MAXC * KSPLIT];
__device__ float g_part_o[MAXC * KSPLIT];

// ---- Kernel A: fused partial reductions + structured ones-fill -------------
__global__ void __launch_bounds__(256) fused_reduce_fill(
    const float* __restrict__ U,
    const float* __restrict__ O,
    const float* __restrict__ pw,
    const float* __restrict__ nw,
    const float2* __restrict__ itv,
    float* __restrict__ out,
    int K, int ncols, int rpb, int RX, unsigned RBLOCKS,
    int hshift, unsigned ne4, unsigned totF4)
{
    unsigned bid = blockIdx.x;

    if (bid < RBLOCKS) {
        // ---------------- reduction part (read-bound) ----------------
        int bx = (int)(bid % (unsigned)RX);
        int by = (int)(bid / (unsigned)RX);
        int j  = bx * 256 + (int)threadIdx.x;
        if (j >= ncols) return;                       // exit counts as trigger
        int k0 = by * rpb;
        int k1 = min(k0 + rpb, K);

        float au0 = 0.f, au1 = 0.f, ao0 = 0.f, ao1 = 0.f;
        size_t base = (size_t)k0 * (size_t)ncols + (size_t)j;
        int k = k0;
        #pragma unroll 4
        for (; k + 1 < k1; k += 2, base += 2 * (size_t)ncols) {
            float u0 = __ldg(U + base);
            float o0 = __ldg(O + base);
            float u1 = __ldg(U + base + ncols);
            float o1 = __ldg(O + base + ncols);
            float p0 = __ldg(pw + k);
            float n0 = __ldg(nw + k);
            float p1 = __ldg(pw + k + 1);
            float n1 = __ldg(nw + k + 1);
            au0 = fmaf(p0, u0, au0);  au0 = fmaf(n0, o0, au0);
            ao0 = fmaf(n0, u0, ao0);  ao0 = fmaf(p0, o0, ao0);
            au1 = fmaf(p1, u1, au1);  au1 = fmaf(n1, o1, au1);
            ao1 = fmaf(n1, u1, ao1);  ao1 = fmaf(p1, o1, ao1);
        }
        if (k < k1) {
            float u = __ldg(U + base), o = __ldg(O + base);
            float p = __ldg(pw + k),   n = __ldg(nw + k);
            au0 = fmaf(p, u, au0);  au0 = fmaf(n, o, au0);
            ao0 = fmaf(n, u, ao0);  ao0 = fmaf(p, o, ao0);
        }
        // keep partials L2-resident for the finalize
        __stcg(&g_part_u[(size_t)j * KSPLIT + by], au0 + au1);
        __stcg(&g_part_o[(size_t)j * KSPLIT + by], ao0 + ao1);
        cudaTriggerProgrammaticLaunchCompletion();    // partials are pre-trigger
        return;
    }

    // ---------------- fill part (write-bound) — proven R5 path ----------------
    unsigned f = (bid - RBLOCKS) * 256u + threadIdx.x;   // float4 index
    if (f >= totF4) return;

    float4 v = make_float4(1.f, 1.f, 1.f, 1.f);

    if (f < 2u * ne4) {
        unsigned a   = (f >= ne4) ? 1u : 0u;                // 0 = under, 1 = over
        unsigned idx = f - a * ne4;
        unsigned b   = idx >> hshift;                       // block
        unsigned fi  = idx & ((1u << hshift) - 1u);         // float4 within block

        if (fi == 0) {
            // rows 0 (coeff — placeholder, overwritten by finalize) and 1
            if (b == 1) { float2 t = __ldg(itv + 1); v.z = t.x; v.w = t.y; }
        } else {
            unsigned i0 = 2u * fi;                          // rows i0, i0+1
            if (b == i0)          { float2 t = __ldg(itv + i0);     v.x = t.x; v.y = t.y; }
            else if (b == i0 + 1) { float2 t = __ldg(itv + i0 + 1); v.z = t.x; v.w = t.y; }
        }
    }
    // f in [2*ne4, totF4): degree ones — v stays {1,1,1,1}

    // streaming store: never re-read, evict-first so partials stay cached
    __stcs(reinterpret_cast<float4*>(out) + f, v);

    // trigger AFTER the store: all placeholder writes are pre-trigger, so
    // finalize's coeff overwrites are ordered after them.
    cudaTriggerProgrammaticLaunchCompletion();
}

// ---- Kernel B: warp-per-column fold + bias + coeff rows (PDL dependent) ----
__global__ void __launch_bounds__(256) finalize(
    const float* __restrict__ bias,
    const float2* __restrict__ itv,
    float* __restrict__ out,
    int ncols, int n_vars)
{
    int warp = (blockIdx.x * 256 + threadIdx.x) >> 5;   // one warp per column
    int lane = threadIdx.x & 31;
    int j = warp;
    const float* pu = g_part_u + (size_t)j * KSPLIT;
    const float* po = g_part_o + (size_t)j * KSPLIT;

    // park until primary grid has triggered everywhere (acquire semantics)
    cudaGridDependencySynchronize();

    if (warp >= ncols) return;

    float su = __ldg(pu + lane) + __ldg(pu + lane + 32);
    float so = __ldg(po + lane) + __ldg(po + lane + 32);

    #pragma unroll
    for (int off = 16; off > 0; off >>= 1) {
        su += __shfl_xor_sync(0xFFFFFFFFu, su, off);
        so += __shfl_xor_sync(0xFFFFFFFFu, so, off);
    }

    if (lane == 0) {
        float bs = bias[0];
        su += bs;  so += bs;

        float2 vu, vo;
        if (j == 0) {
            float2 t0 = __ldg(itv);
            vu = make_float2(su * t0.x, su * t0.y);
            vo = make_float2(so * t0.x, so * t0.y);
        } else {
            vu = make_float2(su, su);
            vo = make_float2(so, so);
        }

        size_t NE2 = (size_t)ncols * (size_t)n_vars;   // float2s per ibf array
        float2* o2 = reinterpret_cast<float2*>(out);
        o2[(size_t)j * (size_t)n_vars]       = vu;
        o2[NE2 + (size_t)j * (size_t)n_vars] = vo;
    }
}

// ---------------------------------------------------------------------------
extern "C" void kernel_launch(void* const* d_in, const int* in_sizes, int n_in,
                              void* d_out, int out_size)
{
    const float* U    = (const float*)d_in[0];   // layer_inputs_under  (K, n+1)
    const float* O    = (const float*)d_in[1];   // layer_inputs_over   (K, n+1)
    const float* itv  = (const float*)d_in[4];   // intervals (n, 2)
    const float* pw   = (const float*)d_in[5];   // node_pos_weights (K,)
    const float* nw   = (const float*)d_in[6];   // node_neg_weights (K,)
    const float* bias = (const float*)d_in[7];   // node_bias (1,)
    float* out = (float*)d_out;

    const int n_vars = in_sizes[2];              // 4096
    const int K      = in_sizes[5];              // 4096
    const int ncols  = n_vars + 1;

    // reduction geometry
    const int RX  = (ncols + 255) / 256;
    const int rpb = (K + KSPLIT - 1) / KSPLIT;
    const unsigned RBLOCKS = (unsigned)(RX * KSPLIT);

    // fill geometry (n_vars power of two; half = n_vars/2 float4s per block)
    unsigned half = (unsigned)(n_vars >> 1);
    int hshift = 0;
    while ((1u << hshift) < half) ++hshift;
    unsigned ne4   = (unsigned)ncols * half;               // float4s per ibf array
    unsigned degF4 = (unsigned)(2 * n_vars) / 4u;          // degree float4s
    unsigned totF4 = 2u * ne4 + degF4;

    unsigned fillBlocks = (totF4 + 255u) / 256u;
    dim3 gridA(RBLOCKS + fillBlocks);

    fused_reduce_fill<<<gridA, 256>>>(U, O, pw, nw, (const float2*)itv, out,
                                      K, ncols, rpb, RX, RBLOCKS,
                                      hshift, ne4, totF4);

    // finalize: one warp per column, PDL so it parks on-SM during kernel A
    int finThreads = ncols * 32;
    unsigned finBlocks = (unsigned)((finThreads + 255) / 256);

    cudaLaunchConfig_t cfg = {};
    cfg.gridDim  = dim3(finBlocks);
    cfg.blockDim = dim3(256);
    cfg.dynamicSmemBytes = 0;
    cfg.stream = (cudaStream_t)0;                // legacy default (capture) stream
    cudaLaunchAttribute attrs[1];
    attrs[0].id = cudaLaunchAttributeProgrammaticStreamSerialization;
    attrs[0].val.programmaticStreamSerializationAllowed = 1;
    cfg.attrs = attrs;
    cfg.numAttrs = 1;
    cudaLaunchKernelEx(&cfg, finalize, bias, (const float2*)itv, out,
                       ncols, n_vars);
}

// round 14
// speedup vs baseline: 1.4158x; 1.4158x over previous
#include <cuda_runtime.h>

// ---------------------------------------------------------------------------
// NodeModule_4432406249918  (GB300 / sm_103a)  — R5 structure (best known),
// fill blocks widened to 4 chunks (4 coalesced float4 stores per thread).
//   Kernel A: fused reduce + fill. Reduce identical to R5. Fill: each block
//             covers 1024 float4s as 4 fully-coalesced 256-float4 chunks.
//   Kernel B: warp-per-column finalize (R5-identical).
//
// out = [ input_under ((n+1)*n,2) | input_over ((n+1)*n,2) | ones(n) | ones(n) ]
//   under_coeffs[j] = sum_k ( nw[k]*Over[k][j] + pw[k]*Under[k][j] ) + bias
//   over_coeffs [j] = sum_k ( pw[k]*Over[k][j] + nw[k]*Under[k][j] ) + bias
//   block b, row i, col c:
//     i==0           -> coeffs[b] * (b==0 ? intervals[0][c] : 1)
//     i==b (0<i<n)   -> intervals[i][c]
//     else           -> 1
// ---------------------------------------------------------------------------

#define KSPLIT 64
#define MAXC   8192   // >= n_vars+1
#define FCHUNK 4      // float4-chunks per fill block

// transposed: g_part_*[j * KSPLIT + y]  (finalize reads coalesce per warp)
__device__ float g_part_u[MAXC * KSPLIT];
__device__ float g_part_o[MAXC * KSPLIT];

// ---- Kernel A: fused partial reductions + structured ones-fill -------------
__global__ void __launch_bounds__(256) fused_reduce_fill(
    const float* __restrict__ U,
    const float* __restrict__ O,
    const float* __restrict__ pw,
    const float* __restrict__ nw,
    const float2* __restrict__ itv,
    float* __restrict__ out,
    int K, int ncols, int rpb, int RX, unsigned RBLOCKS,
    int hshift, unsigned ne4, unsigned totF4)
{
    unsigned bid = blockIdx.x;

    if (bid < RBLOCKS) {
        // ---------------- reduction part (read-bound) — R5-identical ---------
        int bx = (int)(bid % (unsigned)RX);
        int by = (int)(bid / (unsigned)RX);
        int j  = bx * 256 + (int)threadIdx.x;
        if (j >= ncols) return;
        int k0 = by * rpb;
        int k1 = min(k0 + rpb, K);

        float au0 = 0.f, au1 = 0.f, ao0 = 0.f, ao1 = 0.f;
        size_t base = (size_t)k0 * (size_t)ncols + (size_t)j;
        int k = k0;
        #pragma unroll 4
        for (; k + 1 < k1; k += 2, base += 2 * (size_t)ncols) {
            float u0 = __ldg(U + base);
            float o0 = __ldg(O + base);
            float u1 = __ldg(U + base + ncols);
            float o1 = __ldg(O + base + ncols);
            float p0 = __ldg(pw + k);
            float n0 = __ldg(nw + k);
            float p1 = __ldg(pw + k + 1);
            float n1 = __ldg(nw + k + 1);
            au0 = fmaf(p0, u0, au0);  au0 = fmaf(n0, o0, au0);
            ao0 = fmaf(n0, u0, ao0);  ao0 = fmaf(p0, o0, ao0);
            au1 = fmaf(p1, u1, au1);  au1 = fmaf(n1, o1, au1);
            ao1 = fmaf(n1, u1, ao1);  ao1 = fmaf(p1, o1, ao1);
        }
        if (k < k1) {
            float u = __ldg(U + base), o = __ldg(O + base);
            float p = __ldg(pw + k),   n = __ldg(nw + k);
            au0 = fmaf(p, u, au0);  au0 = fmaf(n, o, au0);
            ao0 = fmaf(n, u, ao0);  ao0 = fmaf(p, o, ao0);
        }
        // keep partials L2-resident for the finalize
        __stcg(&g_part_u[(size_t)j * KSPLIT + by], au0 + au1);
        __stcg(&g_part_o[(size_t)j * KSPLIT + by], ao0 + ao1);
        return;
    }

    // ---------------- fill part (write-bound): 4 coalesced chunks ------------
    unsigned fbase = (bid - RBLOCKS) * (256u * FCHUNK) + threadIdx.x;

    #pragma unroll
    for (int c = 0; c < FCHUNK; ++c) {
        unsigned f = fbase + (unsigned)c * 256u;        // float4 index
        if (f >= totF4) return;

        float4 v = make_float4(1.f, 1.f, 1.f, 1.f);

        if (f < 2u * ne4) {
            unsigned a   = (f >= ne4) ? 1u : 0u;            // 0 = under, 1 = over
            unsigned idx = f - a * ne4;
            unsigned b   = idx >> hshift;                   // block
            unsigned fi  = idx & ((1u << hshift) - 1u);     // float4 within block

            if (fi == 0) {
                // rows 0 (coeff — placeholder, overwritten by finalize) and 1
                if (b == 1) { float2 t = __ldg(itv + 1); v.z = t.x; v.w = t.y; }
            } else {
                unsigned i0 = 2u * fi;                      // rows i0, i0+1
                if (b == i0)          { float2 t = __ldg(itv + i0);     v.x = t.x; v.y = t.y; }
                else if (b == i0 + 1) { float2 t = __ldg(itv + i0 + 1); v.z = t.x; v.w = t.y; }
            }
        }
        // f in [2*ne4, totF4): degree ones — v stays {1,1,1,1}

        // streaming store: never re-read, evict-first so partials stay cached
        __stcs(reinterpret_cast<float4*>(out) + f, v);
    }
}

// ---- Kernel B: warp-per-column fold + bias + coeff rows (R5-identical) -----
__global__ void __launch_bounds__(256) finalize(
    const float* __restrict__ bias,
    const float2* __restrict__ itv,
    float* __restrict__ out,
    int ncols, int n_vars)
{
    int warp = (blockIdx.x * 256 + threadIdx.x) >> 5;   // one warp per column
    int lane = threadIdx.x & 31;
    if (warp >= ncols) return;
    int j = warp;

    const float* pu = g_part_u + (size_t)j * KSPLIT;
    const float* po = g_part_o + (size_t)j * KSPLIT;
    float su = __ldg(pu + lane) + __ldg(pu + lane + 32);
    float so = __ldg(po + lane) + __ldg(po + lane + 32);

    #pragma unroll
    for (int off = 16; off > 0; off >>= 1) {
        su += __shfl_xor_sync(0xFFFFFFFFu, su, off);
        so += __shfl_xor_sync(0xFFFFFFFFu, so, off);
    }

    if (lane == 0) {
        float bs = bias[0];
        su += bs;  so += bs;

        float2 vu, vo;
        if (j == 0) {
            float2 t0 = __ldg(itv);
            vu = make_float2(su * t0.x, su * t0.y);
            vo = make_float2(so * t0.x, so * t0.y);
        } else {
            vu = make_float2(su, su);
            vo = make_float2(so, so);
        }

        size_t NE2 = (size_t)ncols * (size_t)n_vars;   // float2s per ibf array
        float2* o2 = reinterpret_cast<float2*>(out);
        o2[(size_t)j * (size_t)n_vars]       = vu;
        o2[NE2 + (size_t)j * (size_t)n_vars] = vo;
    }
}

// ---------------------------------------------------------------------------
extern "C" void kernel_launch(void* const* d_in, const int* in_sizes, int n_in,
                              void* d_out, int out_size)
{
    const float* U    = (const float*)d_in[0];   // layer_inputs_under  (K, n+1)
    const float* O    = (const float*)d_in[1];   // layer_inputs_over   (K, n+1)
    const float* itv  = (const float*)d_in[4];   // intervals (n, 2)
    const float* pw   = (const float*)d_in[5];   // node_pos_weights (K,)
    const float* nw   = (const float*)d_in[6];   // node_neg_weights (K,)
    const float* bias = (const float*)d_in[7];   // node_bias (1,)
    float* out = (float*)d_out;

    const int n_vars = in_sizes[2];              // 4096
    const int K      = in_sizes[5];              // 4096
    const int ncols  = n_vars + 1;

    // reduction geometry
    const int RX  = (ncols + 255) / 256;
    const int rpb = (K + KSPLIT - 1) / KSPLIT;
    const unsigned RBLOCKS = (unsigned)(RX * KSPLIT);

    // fill geometry (n_vars power of two; half = n_vars/2 float4s per block)
    unsigned half = (unsigned)(n_vars >> 1);
    int hshift = 0;
    while ((1u << hshift) < half) ++hshift;
    unsigned ne4   = (unsigned)ncols * half;               // float4s per ibf array
    unsigned degF4 = (unsigned)(2 * n_vars) / 4u;          // degree float4s
    unsigned totF4 = 2u * ne4 + degF4;

    unsigned perBlock   = 256u * FCHUNK;
    unsigned fillBlocks = (totF4 + perBlock - 1u) / perBlock;
    dim3 gridA(RBLOCKS + fillBlocks);

    fused_reduce_fill<<<gridA, 256>>>(U, O, pw, nw, (const float2*)itv, out,
                                      K, ncols, rpb, RX, RBLOCKS,
                                      hshift, ne4, totF4);

    // one warp per column
    int finThreads = ncols * 32;
    finalize<<<(finThreads + 255) / 256, 256>>>(bias, (const float2*)itv, out,
                                                ncols, n_vars);
}